// round 2
// baseline (speedup 1.0000x reference)
#include <cuda_runtime.h>
#include <cstdint>

// ---------------- problem constants ----------------
#define BB 4
#define NN 6
#define DD 41
#define FH 16
#define FW 44
#define CC 64
#define NX 200
#define NY 200
#define NP (BB*NN*DD*FH*FW)        // 692736 points (exactly 21648 warps of 32)
#define PTS_PER_BN (DD*FH*FW)      // 28864
#define SPATIAL (NX*NY)            // 40000

// scratch accumulator, channel-last: (B, NX, NY, C).
// INVARIANT: zero at entry to kernel_launch. Zero-initialized at module load;
// transpose_zero_kernel re-zeroes it after reading, so every full launch
// restores the invariant (graph replays stay deterministic).
__device__ __align__(16) float g_scratch[BB * SPATIAL * CC];
// per-(b,n) params: comb[9], invPostRots[9], post_trans[3], trans[3] = 24 floats
__device__ float g_params[BB * NN * 24];

// ---------------- 3x3 inverse (adjugate) ----------------
__device__ __forceinline__ void inv3(const float* m, float* o) {
    float a=m[0],b=m[1],c=m[2],d=m[3],e=m[4],f=m[5],g=m[6],h=m[7],i=m[8];
    float A  =  (e*i - f*h);
    float Bm = -(d*i - f*g);
    float Cm =  (d*h - e*g);
    float det = a*A + b*Bm + c*Cm;
    float inv = 1.0f / det;
    o[0] =  A*inv;
    o[1] = -(b*i - c*h)*inv;
    o[2] =  (b*f - c*e)*inv;
    o[3] =  Bm*inv;
    o[4] =  (a*i - c*g)*inv;
    o[5] = -(a*f - c*d)*inv;
    o[6] =  Cm*inv;
    o[7] = -(a*h - b*g)*inv;
    o[8] =  (a*e - b*d)*inv;
}

// ---------------- precompute per-(b,n) transforms ----------------
__global__ void precompute_kernel(const float* __restrict__ rots,
                                  const float* __restrict__ intrins,
                                  const float* __restrict__ post_rots,
                                  const float* __restrict__ trans,
                                  const float* __restrict__ post_trans) {
    int i = threadIdx.x;
    if (i >= BB*NN) return;
    const float* R  = rots      + i*9;
    const float* K  = intrins   + i*9;
    const float* PR = post_rots + i*9;

    float iK[9], iPR[9], comb[9];
    inv3(K, iK);
    inv3(PR, iPR);
    #pragma unroll
    for (int r = 0; r < 3; r++)
        #pragma unroll
        for (int c = 0; c < 3; c++)
            comb[r*3+c] = R[r*3+0]*iK[0*3+c] + R[r*3+1]*iK[1*3+c] + R[r*3+2]*iK[2*3+c];

    float* o = g_params + i*24;
    #pragma unroll
    for (int k = 0; k < 9; k++) o[k]   = comb[k];
    #pragma unroll
    for (int k = 0; k < 9; k++) o[9+k] = iPR[k];
    o[18] = post_trans[i*3+0]; o[19] = post_trans[i*3+1]; o[20] = post_trans[i*3+2];
    o[21] = trans[i*3+0];      o[22] = trans[i*3+1];      o[23] = trans[i*3+2];
}

// ---------------- fused geometry + scatter-add ----------------
// One warp owns 32 consecutive points.
// Phase 1: lane l computes the voxel destination offset for point p0+l (or -1).
// Phase 2: 16 iterations; half-warps pair up (16 lanes per point) to move the
//          256B feature row with one float4 load + one red.global.add.v4.f32.
__global__ void scatter_kernel(const float* __restrict__ x) {
    int gwid = (blockIdx.x * blockDim.x + threadIdx.x) >> 5;
    int lane = threadIdx.x & 31;
    int p0   = gwid * 32;
    int p    = p0 + lane;

    // ---- phase 1: per-lane geometry for its own point ----
    int bn  = p / PTS_PER_BN;
    int rem = p - bn * PTS_PER_BN;
    int d   = rem / (FH*FW);
    int hw  = rem - d * (FH*FW);
    int h   = hw / FW;
    int w   = hw - h * FW;
    int b   = bn / NN;

    const float* prm = g_params + bn*24;

    float u   = (float)w * (351.0f / 43.0f);
    float v   = (float)h * (127.0f / 15.0f);
    float dep = 4.0f + (float)d;

    float px = u   - prm[18];
    float py = v   - prm[19];
    float pz = dep - prm[20];
    float qx = prm[9]*px  + prm[10]*py + prm[11]*pz;
    float qy = prm[12]*px + prm[13]*py + prm[14]*pz;
    float qz = prm[15]*px + prm[16]*py + prm[17]*pz;
    float sx = qx * qz;
    float sy = qy * qz;
    float sz = qz;
    float gx = prm[0]*sx + prm[1]*sy + prm[2]*sz + prm[21];
    float gy = prm[3]*sx + prm[4]*sy + prm[5]*sz + prm[22];
    float gz = prm[6]*sx + prm[7]*sy + prm[8]*sz + prm[23];

    int ix = (int)((gx + 50.0f) / 0.5f);
    int iy = (int)((gy + 50.0f) / 0.5f);
    int iz = (int)((gz + 10.0f) / 20.0f);

    int idx = -1;
    if (ix >= 0 && ix < NX && iy >= 0 && iy < NY && iz == 0)
        idx = ((b*NX + ix)*NY + iy) * CC;

    // ---- phase 2: feature movement, 2 points per iteration ----
    int half = lane >> 4;        // 0 or 1: which of the 2 points this half-warp handles
    int l16  = lane & 15;        // float4 slot within the 64-channel row
    #pragma unroll 4
    for (int i = 0; i < 16; i++) {
        int pa  = 2*i + half;
        int dst = __shfl_sync(0xffffffffu, idx, pa);
        if (dst >= 0) {
            float4 val = __ldg(reinterpret_cast<const float4*>(x + (size_t)(p0 + pa) * CC) + l16);
            float* dp  = g_scratch + (size_t)dst + l16*4;
            asm volatile("red.global.add.v4.f32 [%0], {%1, %2, %3, %4};"
                         :: "l"(dp), "f"(val.x), "f"(val.y), "f"(val.z), "f"(val.w)
                         : "memory");
        }
    }
}

// ---------------- transpose (B, S, C) -> (B, C, S) + re-zero scratch ----------------
// One block owns a full 32-spatial x 64-channel scratch tile (exclusive),
// so it can safely zero it after reading.
__global__ void transpose_zero_kernel(float* __restrict__ out) {
    __shared__ float tile[CC][33];
    int b   = blockIdx.y;
    int s0  = blockIdx.x * 32;
    int tid = threadIdx.x;           // 0..255

    float4* src = reinterpret_cast<float4*>(g_scratch + ((size_t)b * SPATIAL + s0) * CC);
    const float4 z4 = make_float4(0.f, 0.f, 0.f, 0.f);
    #pragma unroll
    for (int i = 0; i < 2; i++) {
        int j  = tid + i*256;        // 0..511 float4s (32 s-rows x 16 float4)
        int sl = j >> 4;             // spatial within tile
        int c4 = j & 15;             // float4 within channel row
        float4 v = src[j];
        tile[c4*4+0][sl] = v.x;
        tile[c4*4+1][sl] = v.y;
        tile[c4*4+2][sl] = v.z;
        tile[c4*4+3][sl] = v.w;
        src[j] = z4;                 // restore zero-invariant (L2-hit, line just read)
    }
    __syncthreads();

    float* dst = out + (size_t)b * CC * SPATIAL + s0;
    int lanes = tid & 31;
    int wrp   = tid >> 5;            // 0..7
    #pragma unroll
    for (int i = 0; i < 8; i++) {
        int c = wrp + i*8;
        dst[(size_t)c * SPATIAL + lanes] = tile[c][lanes];
    }
}

// ---------------- launch ----------------
extern "C" void kernel_launch(void* const* d_in, const int* in_sizes, int n_in,
                              void* d_out, int out_size) {
    const float* x          = (const float*)d_in[0];
    const float* rots       = (const float*)d_in[1];
    const float* trans      = (const float*)d_in[2];
    const float* intrins    = (const float*)d_in[3];
    const float* post_rots  = (const float*)d_in[4];
    const float* post_trans = (const float*)d_in[5];
    float* out = (float*)d_out;

    precompute_kernel<<<1, 32>>>(rots, intrins, post_rots, trans, post_trans);

    // 692736 points / 32 per warp = 21648 warps; 8 warps/block -> 2706 blocks
    scatter_kernel<<<2706, 256>>>(x);

    // S=40000 -> 1250 tiles of 32 spatial x full 64 channels; B=4
    transpose_zero_kernel<<<dim3(1250, 4), 256>>>(out);
}